// round 10
// baseline (speedup 1.0000x reference)
#include <cuda_runtime.h>

// Radon forward projection, phase-split + row-pair-float2 formulation.
// out[b,a,s] = sum_t bilinear(imgs[b], x(s,t), y(s,t)),
// x = s*cos - t*sin + c ; y = s*sin + t*cos + c ; c = 127.5.
//
// Kernel 1: block = (b, angle-pair, phase), 8640 blocks, 512 threads
// (2 angles x 256 detectors). Phase p owns y0i in a 23-row band (24 for p0).
// Tile rows are float2 ROW PAIRS: tile[r][x] = (img[base+r][x], img[base+r+1][x])
// so each bilinear sample needs only 2x LDS.64 instead of 4x LDS.32.
// 24 rows x 287 float2 = 55.1 KB dynamic smem -> 4 CTAs/SM (64 warps, 100%
// occupancy cap; this round's lever — R6 evidence says latency-hiding bound).
//
// Ownership is EXACT: band p owns yv = y+1 in [lo_p, hi_p), integer float
// bounds, tested on the SAME fmaf(tf,ca,ys1) everywhere. Monotone yv(t):
// conservative analytic entry/exit estimates refined by exact scans -> a
// branchless counted inner loop. The exit-scan start is clamped to txhi+1
// (R8 fix) so window-limited rays count exactly txhi+1-t iterations — all
// counted iterations are provably in-band AND in-window (staged memory).
// Guard-shifted coords xv = x+5 (trunc; eps<0 lands on zero guard cols),
// yv = y+1 >= 0 in-band. x outside the window hits zero guard cols -> 0.

#define B_ 8
#define N_ 256
#define A_ 180

constexpr int PAIRS      = A_ / 2;            // 90
constexpr int BAND       = 23;
constexpr int PHASES     = 12;                // ceil(257/23)
constexpr int STRIDE     = 287;               // float2 elements per tile row
constexpr int TROWS      = 24;                // row-pairs: covers BAND+1 rows
constexpr int SMEM_BYTES = TROWS * STRIDE * 8;    // 55,104 B -> 4 CTAs/SM
constexpr int NBLK       = B_ * PAIRS * PHASES;   // 8640

__device__ float g_partial[NBLK * 512];       // 17.7 MB static scratch

__global__ __launch_bounds__(512, 4)
void radon_phase_kernel(const float* __restrict__ imgs,
                        const float* __restrict__ angles)
{
    extern __shared__ float2 tile[];

    const int tid  = threadIdx.x;
    const int blk  = blockIdx.x;
    const int p    = blk % PHASES;
    const int bp   = blk / PHASES;            // b*PAIRS + pair
    const int b    = bp / PAIRS;
    const int pr   = bp - b * PAIRS;
    const int al   = tid >> 8;                // which angle of the pair
    const int s    = tid & 255;               // detector index
    const int warp = tid >> 5;
    const int lane = tid & 31;

    const float ang = angles[pr * 2 + al];
    const float ca  = cosf(ang);
    const float sa  = sinf(ang);
    const float sf  = (float)s - 127.5f;
    const float xs  = fmaf(sf, ca, 127.5f);
    const float xs5 = xs + 5.0f;              // guard-shifted x origin
    const float ys1 = fmaf(sf, sa, 127.5f) + 1.0f;   // guard-shifted y origin
    const float nsa = -sa;
    const bool  up  = (ca >= 0.0f);           // yv non-decreasing in t?

    // yv endpoints (same fmaf form as the loop) for exact band pre-check
    const float yA    = fmaf(-127.5f, ca, ys1);
    const float yB    = fmaf( 127.5f, ca, ys1);
    const float yvmin = fminf(yA, yB);
    const float yvmax = fmaxf(yA, yB);

    // Owned band in yv space: floor(yv) in [lo, hi-1].
    // p=0: y0i in [-1,22]          -> yv in [0,24).
    // p>0: y0i in [23p, 23p+22]    -> yv in [23p+1, 23p+24). Exact int bounds.
    const float lo = (p == 0) ? 0.0f : (float)(BAND * p + 1);
    const float hi = (float)(BAND * p + 24);

    // block-wide empty-band early out (skip staging entirely)
    const bool hit = (yvmax >= lo) & (yvmin < hi);
    if (!__syncthreads_or(hit)) {
        g_partial[blk * 512 + tid] = 0.0f;
        return;
    }

    // ---- stage row-pair tile: tile[r][c] = (img[base+r][c-5], img[base+r+1][c-5])
    const int base = BAND * p - 1;            // image row of tile row r=0 (.x half)
    const float* __restrict__ img = imgs + b * N_ * N_;
    for (int r = warp; r < TROWS; r += 16) {
        const int ir0 = base + r;
        const int ir1 = ir0 + 1;
        const bool v0ok = (unsigned)ir0 < (unsigned)N_;
        const bool v1ok = (unsigned)ir1 < (unsigned)N_;
        const float* s0 = img + ir0 * N_;
        const float* s1 = img + ir1 * N_;
        float2* dst = tile + r * STRIDE;
        for (int c = lane; c < STRIDE; c += 32) {
            int ic = c - 5;
            bool cin = (unsigned)ic < (unsigned)N_;
            float v0 = (v0ok && cin) ? s0[ic] : 0.0f;
            float v1 = (v1ok && cin) ? s1[ic] : 0.0f;
            dst[c] = make_float2(v0, v1);
        }
    }
    __syncthreads();

    float acc = 0.0f;

    if (hit) {
        // analytic helpers (conservative only; exactness from scans)
        const float inv_ca = 1.0f / ((ca == 0.0f) ? 1e-30f : ca);
        const float inv_sa = 1.0f / ((sa == 0.0f) ? 1e-30f : sa);

        // x-window: x outside (-3,259) padded +-2 -> both sampled cols are
        // zero guards -> exactly 0. Inside: xv = x+5 in (-0.01, 266.01).
        float tca = (xs + 3.0f)   * inv_sa;
        float tcb = (xs - 259.0f) * inv_sa;
        const int txlo = (int)fmaxf(floorf(fminf(tca, tcb) + 127.5f) - 2.0f, 0.0f);
        const int txhi = (int)fminf(ceilf (fmaxf(tca, tcb) + 127.5f) + 2.0f, 255.0f);

        // conservative analytic entry (pad -2, never late), exact entry scan
        const float Lb = up ? lo : hi;
        float t_ent = fmaf(Lb - ys1, inv_ca, 127.5f);
        int t = max((int)fmaxf(fminf(floorf(t_ent) - 2.0f, 255.0f), 0.0f), txlo);
        float tf = (float)t - 127.5f;
        for (; t <= txhi; ++t, tf += 1.0f) {
            float yv = fmaf(tf, ca, ys1);
            if (up ? (yv >= lo) : (yv < hi)) break;
        }

        int n = 0;
        if (t <= txhi) {
            // conservative analytic exit (pad -2, never late), exact exit
            // scan; start clamped to txhi+1 (in float, before the int cast)
            // so a window-limited ray counts exactly txhi+1-t iterations.
            const float Ub = up ? hi : lo;
            float t_xt = fmaf(Ub - ys1, inv_ca, 127.5f);
            float te_f = fmaxf(fminf(floorf(t_xt) - 2.0f, (float)(txhi + 1)),
                               (float)t);
            int te = (int)te_f;
            float tfe = (float)te - 127.5f;
            for (; te <= txhi; ++te, tfe += 1.0f) {
                float yv = fmaf(tfe, ca, ys1);
                if (up ? (yv >= hi) : (yv < lo)) break;   // first t past band
            }
            n = te - t;     // owned iterations: t .. te-1 (in-band, in-window)
        }

        // fold the band row offset into the base pointer:
        // row index = floor(yv) - 23p; idx = (floor(yv)-23p)*287 + xi
        const float2* __restrict__ tb = tile - (BAND * p) * STRIDE;

        #pragma unroll 4
        for (int k = 0; k < n; ++k) {
            float yv = fmaf(tf, ca, ys1);
            float xv = fmaf(tf, nsa, xs5);
            float fy = truncf(yv);            // yv >= 0 in-band: trunc == floor
            float fx = truncf(xv);            // eps<0 -> col 0 zero guard
            float wy = yv - fy;
            float wx = xv - fx;
            int idx  = (int)fmaf(fy, (float)STRIDE, fx);   // exact (< 2^24)

            float2 v0 = tb[idx];              // (a00, a10)
            float2 v1 = tb[idx + 1];          // (a01, a11)

            float h0 = fmaf(wx, v1.x - v0.x, v0.x);
            float h1 = fmaf(wx, v1.y - v0.y, v0.y);
            acc += fmaf(wy, h1 - h0, h0);
            tf += 1.0f;
        }
    }

    g_partial[blk * 512 + tid] = acc;
}

// Kernel 2: out[b, 2*pr+al, s] = sum_p partial[((b*90+pr)*12+p)*512 + al*256 + s]
__global__ __launch_bounds__(256)
void radon_reduce_kernel(float* __restrict__ out)
{
    const int o  = blockIdx.x * 256 + threadIdx.x;   // 368,640 outputs
    const int s  = o & 255;
    const int ba = o >> 8;
    const int a  = ba % A_;
    const int b  = ba / A_;
    const int pr = a >> 1;
    const int al = a & 1;

    const float* p = g_partial + ((b * PAIRS + pr) * PHASES) * 512 + al * 256 + s;
    float acc = 0.0f;
    #pragma unroll
    for (int k = 0; k < PHASES; ++k) acc += p[k * 512];
    out[o] = acc;
}

extern "C" void kernel_launch(void* const* d_in, const int* in_sizes, int n_in,
                              void* d_out, int out_size)
{
    const float* imgs   = (const float*)d_in[0];
    const float* angles = (const float*)d_in[1];
    float*       out    = (float*)d_out;

    cudaFuncSetAttribute(radon_phase_kernel,
                         cudaFuncAttributeMaxDynamicSharedMemorySize, SMEM_BYTES);

    radon_phase_kernel<<<NBLK, 512, SMEM_BYTES>>>(imgs, angles);
    radon_reduce_kernel<<<(B_ * A_ * N_) / 256, 256>>>(out);
}

// round 11
// speedup vs baseline: 1.0690x; 1.0690x over previous
#include <cuda_runtime.h>

// Radon forward projection, phase-split + row-pair-float2 + packed-f32x2.
// out[b,a,s] = sum_t bilinear(imgs[b], x(s,t), y(s,t)),
// x = s*cos - t*sin + c ; y = s*sin + t*cos + c ; c = 127.5.
//
// R8 config (proven best): block = (b, angle-pair, phase), 6480 blocks,
// 512 threads (2 angles x 256 detectors). Phase p owns y0i in a 31-row band
// (32 for p0). Tile rows are float2 ROW PAIRS -> 2x LDS.64 per sample.
// 32 x 287 x 8B = 73.5 KB dynamic smem -> 3 CTAs/SM (regs unconstrained; the
// R10 experiment showed forcing 4 CTAs/32 regs regresses).
//
// NEW: inner loop uses sm_103a packed f32x2 ops (fma.rn.f32x2/add.rn.f32x2)
// to compute (yv,xv), (wy,wx), (d0,d1), (h0,h1) pairs 2-for-1. Each packed op
// is bitwise identical to the scalar fmaf/fadd pair it replaces, so the
// exact band-ownership proof (same fmaf yv in scans and loop) is unchanged.
//
// Ownership is EXACT: band p owns yv = y+1 in [lo_p, hi_p), integer float
// bounds, monotone in t; conservative analytic entry/exit + exact scans ->
// branchless counted loop; exit-scan start clamped to txhi+1 (R8 fix) so all
// counted iterations are in-band AND in-window (every smem access staged).
//
// Launch order per call: [noop, phase, reduce, noop] so ncu's "-s 5 -c 1"
// lands on the PHASE kernel (launch #6) instead of the reduce kernel.

#define B_ 8
#define N_ 256
#define A_ 180

constexpr int PAIRS      = A_ / 2;            // 90
constexpr int BAND       = 31;
constexpr int PHASES     = 9;                 // ceil(257/31)
constexpr int STRIDE     = 287;               // float2 elements per tile row
constexpr int TROWS      = 32;                // row-pairs: covers BAND+1 rows
constexpr int SMEM_BYTES = TROWS * STRIDE * 8;    // 73,472 B -> 3 CTAs/SM
constexpr int NBLK       = B_ * PAIRS * PHASES;   // 6480

__device__ float g_partial[NBLK * 512];       // 13.3 MB static scratch

// ---- packed f32x2 helpers (sm_103a FFMA2/FADD2 via PTX) ----
typedef unsigned long long u64;
__device__ __forceinline__ u64 pk2(float lo, float hi) {
    u64 r; asm("mov.b64 %0, {%1, %2};" : "=l"(r) : "f"(lo), "f"(hi)); return r;
}
__device__ __forceinline__ void upk2(u64 v, float& lo, float& hi) {
    asm("mov.b64 {%0, %1}, %2;" : "=f"(lo), "=f"(hi) : "l"(v));
}
__device__ __forceinline__ u64 fma2(u64 a, u64 b, u64 c) {
    u64 d; asm("fma.rn.f32x2 %0, %1, %2, %3;" : "=l"(d) : "l"(a), "l"(b), "l"(c));
    return d;
}
__device__ __forceinline__ u64 add2(u64 a, u64 b) {
    u64 d; asm("add.rn.f32x2 %0, %1, %2;" : "=l"(d) : "l"(a), "l"(b));
    return d;
}

__global__ void radon_noop_kernel() {}

__global__ __launch_bounds__(512, 3)
void radon_phase_kernel(const float* __restrict__ imgs,
                        const float* __restrict__ angles)
{
    extern __shared__ float2 tile[];

    const int tid  = threadIdx.x;
    const int blk  = blockIdx.x;
    const int p    = blk % PHASES;
    const int bp   = blk / PHASES;            // b*PAIRS + pair
    const int b    = bp / PAIRS;
    const int pr   = bp - b * PAIRS;
    const int al   = tid >> 8;                // which angle of the pair
    const int warp = tid >> 5;
    const int lane = tid & 31;

    const float ang = angles[pr * 2 + al];
    const float ca  = cosf(ang);
    const float sa  = sinf(ang);
    const float sf  = (float)(tid & 255) - 127.5f;
    const float xs  = fmaf(sf, ca, 127.5f);
    const float xs5 = xs + 5.0f;              // guard-shifted x origin
    const float ys1 = fmaf(sf, sa, 127.5f) + 1.0f;   // guard-shifted y origin
    const float nsa = -sa;
    const bool  up  = (ca >= 0.0f);           // yv non-decreasing in t?

    // yv endpoints (same fmaf form as the loop) for exact band pre-check
    const float yA    = fmaf(-127.5f, ca, ys1);
    const float yB    = fmaf( 127.5f, ca, ys1);
    const float yvmin = fminf(yA, yB);
    const float yvmax = fmaxf(yA, yB);

    // Owned band in yv space: floor(yv) in [lo, hi-1].
    // p=0: y0i in [-1,30] -> yv in [0,32).
    // p>0: y0i in [31p, 31p+30] -> yv in [31p+1, 31p+32). Exact int bounds.
    const float lo = (p == 0) ? 0.0f : (float)(BAND * p + 1);
    const float hi = (float)(BAND * p + 32);

    // block-wide empty-band early out (skip staging entirely)
    const bool hit = (yvmax >= lo) & (yvmin < hi);
    if (!__syncthreads_or(hit)) {
        g_partial[blk * 512 + tid] = 0.0f;
        return;
    }

    // ---- stage row-pair tile: tile[r][c] = (img[base+r][c-5], img[base+r+1][c-5])
    const int base = BAND * p - 1;            // image row of tile row r=0 (.x half)
    const float* __restrict__ img = imgs + b * N_ * N_;
    for (int r = warp; r < TROWS; r += 16) {
        const int ir0 = base + r;
        const int ir1 = ir0 + 1;
        const bool v0ok = (unsigned)ir0 < (unsigned)N_;
        const bool v1ok = (unsigned)ir1 < (unsigned)N_;
        const float* s0 = img + ir0 * N_;
        const float* s1 = img + ir1 * N_;
        float2* dst = tile + r * STRIDE;
        for (int c = lane; c < STRIDE; c += 32) {
            int ic = c - 5;
            bool cin = (unsigned)ic < (unsigned)N_;
            float v0 = (v0ok && cin) ? s0[ic] : 0.0f;
            float v1 = (v1ok && cin) ? s1[ic] : 0.0f;
            dst[c] = make_float2(v0, v1);
        }
    }
    __syncthreads();

    float acc = 0.0f;

    if (hit) {
        // analytic helpers (conservative only; exactness from scans)
        const float inv_ca = 1.0f / ((ca == 0.0f) ? 1e-30f : ca);
        const float inv_sa = 1.0f / ((sa == 0.0f) ? 1e-30f : sa);

        // x-window: x outside (-3,259) padded +-2 -> both sampled cols are
        // zero guards -> exactly 0. Inside: xv = x+5 in (-0.01, 266.01).
        float tca = (xs + 3.0f)   * inv_sa;
        float tcb = (xs - 259.0f) * inv_sa;
        const int txlo = (int)fmaxf(floorf(fminf(tca, tcb) + 127.5f) - 2.0f, 0.0f);
        const int txhi = (int)fminf(ceilf (fmaxf(tca, tcb) + 127.5f) + 2.0f, 255.0f);

        // conservative analytic entry (pad -2, never late), exact entry scan
        const float Lb = up ? lo : hi;
        float t_ent = fmaf(Lb - ys1, inv_ca, 127.5f);
        int t = max((int)fmaxf(fminf(floorf(t_ent) - 2.0f, 255.0f), 0.0f), txlo);
        float tf = (float)t - 127.5f;
        for (; t <= txhi; ++t, tf += 1.0f) {
            float yv = fmaf(tf, ca, ys1);
            if (up ? (yv >= lo) : (yv < hi)) break;
        }

        int n = 0;
        if (t <= txhi) {
            // conservative analytic exit (pad -2, never late), exact exit
            // scan; start clamped to txhi+1 (in float, before the int cast)
            // so a window-limited ray counts exactly txhi+1-t iterations.
            const float Ub = up ? hi : lo;
            float t_xt = fmaf(Ub - ys1, inv_ca, 127.5f);
            float te_f = fmaxf(fminf(floorf(t_xt) - 2.0f, (float)(txhi + 1)),
                               (float)t);
            int te = (int)te_f;
            float tfe = (float)te - 127.5f;
            for (; te <= txhi; ++te, tfe += 1.0f) {
                float yv = fmaf(tfe, ca, ys1);
                if (up ? (yv >= hi) : (yv < lo)) break;   // first t past band
            }
            n = te - t;     // owned iterations: t .. te-1 (in-band, in-window)
        }

        // fold the band row offset into the base pointer:
        // row index = floor(yv) - 31p; idx = (floor(yv)-31p)*287 + xi
        const u64* __restrict__ tb64 =
            reinterpret_cast<const u64*>(tile) - (BAND * p) * STRIDE;

        // packed constants
        const u64 CANSA = pk2(ca, nsa);       // (ca, -sa)
        const u64 YXS   = pk2(ys1, xs5);      // (y origin, x origin)
        const u64 ONE2  = pk2(1.0f, 1.0f);
        const u64 NEG1  = pk2(-1.0f, -1.0f);
        u64 tf2 = pk2(tf, tf);

        #pragma unroll 4
        for (int k = 0; k < n; ++k) {
            u64 yx = fma2(tf2, CANSA, YXS);   // (yv, xv) — bitwise == scalar fmaf
            float yv, xv; upk2(yx, yv, xv);
            float fy = truncf(yv);            // yv >= 0 in-band: trunc == floor
            float fx = truncf(xv);            // eps<0 -> col 0 zero guard
            u64 wyx = fma2(pk2(fy, fx), NEG1, yx);   // (wy, wx), exact
            float wy, wx; upk2(wyx, wy, wx);
            int idx = (int)fmaf(fy, (float)STRIDE, fx);   // exact (< 2^24)

            u64 v0 = tb64[idx];               // (a00, a10)
            u64 v1 = tb64[idx + 1];           // (a01, a11)

            u64 d = fma2(v0, NEG1, v1);       // (a01-a00, a11-a10)
            u64 h = fma2(pk2(wx, wx), d, v0); // (h0, h1)
            float h0, h1; upk2(h, h0, h1);
            acc += fmaf(wy, h1 - h0, h0);

            tf2 = add2(tf2, ONE2);
        }
    }

    g_partial[blk * 512 + tid] = acc;
}

// Kernel 2: out[b, 2*pr+al, s] = sum_p partial[((b*90+pr)*9+p)*512 + al*256 + s]
__global__ __launch_bounds__(256)
void radon_reduce_kernel(float* __restrict__ out)
{
    const int o  = blockIdx.x * 256 + threadIdx.x;   // 368,640 outputs
    const int s  = o & 255;
    const int ba = o >> 8;
    const int a  = ba % A_;
    const int b  = ba / A_;
    const int pr = a >> 1;
    const int al = a & 1;

    const float* p = g_partial + ((b * PAIRS + pr) * PHASES) * 512 + al * 256 + s;
    float acc = 0.0f;
    #pragma unroll
    for (int k = 0; k < PHASES; ++k) acc += p[k * 512];
    out[o] = acc;
}

extern "C" void kernel_launch(void* const* d_in, const int* in_sizes, int n_in,
                              void* d_out, int out_size)
{
    const float* imgs   = (const float*)d_in[0];
    const float* angles = (const float*)d_in[1];
    float*       out    = (float*)d_out;

    cudaFuncSetAttribute(radon_phase_kernel,
                         cudaFuncAttributeMaxDynamicSharedMemorySize, SMEM_BYTES);

    // Parity padding so ncu's "-s 5 -c 1" captures the PHASE kernel (#6):
    // per call: [noop, phase, reduce, noop] -> launch 6 = call2's phase.
    radon_noop_kernel<<<1, 32>>>();
    radon_phase_kernel<<<NBLK, 512, SMEM_BYTES>>>(imgs, angles);
    radon_reduce_kernel<<<(B_ * A_ * N_) / 256, 256>>>(out);
    radon_noop_kernel<<<1, 32>>>();
}